// round 13
// baseline (speedup 1.0000x reference)
#include <cuda_runtime.h>
#include <math.h>

// Problem constants (fixed by the reference)
#define NN      100000
#define EMAX    1600000
#define FIN     128
#define HCC     64          // heads*hid = 2*32
#define OUTC    40
#define NEG     0.2f
#define BN_EPS  1e-5f
#define SCAN_NB 98          // ceil(NN/1024)

// ---------------- scratch (device globals; no runtime allocation) -----------
__device__ float  g_h  [(size_t)NN * HCC];   // h of current layer
__device__ float  g_x1 [(size_t)NN * HCC];   // x1, later xj = max(x1,x2)
__device__ float2 g_asrc[NN];
__device__ float2 g_adst[NN];
__device__ int    g_rowptr[NN + 1];
__device__ int    g_col[EMAX];
__device__ int    g_deg[NN];
__device__ int    g_cur[NN];
__device__ int    g_bsum[128];
__device__ int    g_boff[128];
__device__ float  g_bns[HCC];
__device__ float  g_bnb[HCC];

// ---------------- BN fold ----------------------------------------------------
__global__ void k_bnprep(const float* __restrict__ gamma, const float* __restrict__ beta,
                         const float* __restrict__ mean,  const float* __restrict__ var)
{
    int c = threadIdx.x;
    if (c < HCC) {
        float s = gamma[c] * rsqrtf(var[c] + BN_EPS);
        g_bns[c] = s;
        g_bnb[c] = beta[c] - mean[c] * s;
    }
}

// ---------------- CSR build --------------------------------------------------
__global__ void k_zero()
{
    int i = blockIdx.x * blockDim.x + threadIdx.x;
    if (i < NN) { g_deg[i] = 0; g_cur[i] = 0; }
}

__global__ void k_hist(const int* __restrict__ dst, int E)
{
    int i = blockIdx.x * blockDim.x + threadIdx.x;
    if (i < E) atomicAdd(&g_deg[dst[i]], 1);
}

// coalesced 3-phase exclusive scan of g_deg -> g_rowptr
__global__ void k_scan1()
{
    __shared__ int ss[1024];
    int t = threadIdx.x;
    int i = blockIdx.x * 1024 + t;
    int d = (i < NN) ? g_deg[i] : 0;
    ss[t] = d;
    __syncthreads();
#pragma unroll
    for (int off = 1; off < 1024; off <<= 1) {
        int v = (t >= off) ? ss[t - off] : 0;
        __syncthreads();
        ss[t] += v;
        __syncthreads();
    }
    if (i < NN) g_rowptr[i] = ss[t] - d;         // block-local exclusive
    if (t == 1023) g_bsum[blockIdx.x] = ss[1023];
}

__global__ void k_scan2()
{
    __shared__ int ss[128];
    int t = threadIdx.x;
    int d = (t < SCAN_NB) ? g_bsum[t] : 0;
    ss[t] = d;
    __syncthreads();
#pragma unroll
    for (int off = 1; off < 128; off <<= 1) {
        int v = (t >= off) ? ss[t - off] : 0;
        __syncthreads();
        ss[t] += v;
        __syncthreads();
    }
    if (t < SCAN_NB) g_boff[t] = ss[t] - d;      // exclusive block offsets
    if (t == 127)    g_rowptr[NN] = ss[127];     // total edge count
}

__global__ void k_scan3()
{
    int i = blockIdx.x * 1024 + threadIdx.x;
    if (i < NN) g_rowptr[i] += g_boff[blockIdx.x];
}

__global__ void k_scatter(const int* __restrict__ src, const int* __restrict__ dst, int E)
{
    int i = blockIdx.x * blockDim.x + threadIdx.x;
    if (i < E) {
        int d = dst[i];
        int p = atomicAdd(&g_cur[d], 1);
        g_col[g_rowptr[d] + p] = src[i];
    }
}

// ---------------- GAT aggregation: one warp per destination node -------------
// Single pass, no segment-max (logits are O(5); exp cannot overflow; softmax is
// shift-invariant so this matches the reference up to rounding).
// mode 0: out = elu(bn(res + b))          (layer 1, writes x1)
// mode 1: out = max(out, res + b)         (layer 2 + JK max, out == x1 buffer)
__global__ void __launch_bounds__(256) k_gat(const float* __restrict__ h,
                                             const float* __restrict__ b,
                                             float* __restrict__ out, int mode)
{
    int n    = (blockIdx.x * blockDim.x + threadIdx.x) >> 5;
    int lane = threadIdx.x & 31;
    if (n >= NN) return;

    int start = g_rowptr[n];
    int end   = g_rowptr[n + 1];
    float2 ad = g_adst[n];

    // self-loop contribution
    float2 asn = g_asrc[n];
    float t0 = asn.x + ad.x, t1 = asn.y + ad.y;
    float e0 = __expf(fmaxf(t0, NEG * t0));
    float e1 = __expf(fmaxf(t1, NEG * t1));
    float den0 = e0, den1 = e1;
    float f0 = e0 * h[(size_t)n * HCC + lane];
    float f1 = e1 * h[(size_t)n * HCC + 32 + lane];

#pragma unroll 4
    for (int k = start; k < end; k++) {
        int s = __ldg(&g_col[k]);                 // uniform -> broadcast
        float2 as = g_asrc[s];                    // uniform -> broadcast
        float u0 = as.x + ad.x, u1 = as.y + ad.y;
        float x0 = __expf(fmaxf(u0, NEG * u0));
        float x1 = __expf(fmaxf(u1, NEG * u1));
        den0 += x0; den1 += x1;
        f0 += x0 * h[(size_t)s * HCC + lane];     // coalesced 128B
        f1 += x1 * h[(size_t)s * HCC + 32 + lane];
    }

    float r0 = f0 / (den0 + 1e-16f);
    float r1 = f1 / (den1 + 1e-16f);

    int c0 = lane, c1 = 32 + lane;
    size_t o0 = (size_t)n * HCC + c0;
    size_t o1 = (size_t)n * HCC + c1;
    if (mode == 0) {
        r0 = (r0 + b[c0]) * g_bns[c0] + g_bnb[c0];
        r1 = (r1 + b[c1]) * g_bns[c1] + g_bnb[c1];
        r0 = r0 > 0.f ? r0 : expm1f(r0);
        r1 = r1 > 0.f ? r1 : expm1f(r1);
        out[o0] = r0;
        out[o1] = r1;
    } else {
        r0 += b[c0];
        r1 += b[c1];
        out[o0] = fmaxf(out[o0], r0);
        out[o1] = fmaxf(out[o1], r1);
    }
}

// ---------------- tiled fp32 GEMM: [N,K] x [K,WC] (+bias) (+fused alpha) -----
// 64-node x CP-col tile, 4x4 micro-tile, FULL K resident in dynamic smem
// (single __syncthreads before compute). When ALPHA, also produces
// g_asrc/g_adst = (out-row) . a_s / a_d per head via shared-atomic reduction.
template<int K, int CP, int WC, bool BIAS, bool ALPHA>
__global__ void k_gemm(const float* __restrict__ A, const float* __restrict__ W,
                       const float* __restrict__ bias, float* __restrict__ Out,
                       const float* __restrict__ a_s, const float* __restrict__ a_d)
{
    extern __shared__ float sm[];
    float* Xs = sm;                 // [K][68]  (stride 68 floats: 16B aligned rows)
    float* Ws = sm + K * 68;        // [K][CP]
    __shared__ float sAs[64][2];
    __shared__ float sAd[64][2];

    const int TX = CP / 4;
    int tid  = threadIdx.x;
    int tx   = tid % TX, ty = tid / TX;
    int base = blockIdx.x * 64;
    int nthr = blockDim.x;

    // fill A tile (coalesced rows), transposed into [k][node]
    for (int idx = tid; idx < 64 * K; idx += nthr) {
        int nl = idx / K, k = idx % K;
        int node = base + nl;
        Xs[k * 68 + nl] = (node < NN) ? A[(size_t)node * K + k] : 0.f;
    }
    // fill W tile
    for (int idx = tid; idx < K * CP; idx += nthr) {
        int k = idx / CP, c = idx % CP;
        Ws[idx] = (c < WC) ? W[(size_t)k * WC + c] : 0.f;
    }
    if (ALPHA && tid < 64) {
        sAs[tid][0] = 0.f; sAs[tid][1] = 0.f;
        sAd[tid][0] = 0.f; sAd[tid][1] = 0.f;
    }
    __syncthreads();

    float acc[4][4];
#pragma unroll
    for (int i = 0; i < 4; i++)
#pragma unroll
        for (int j = 0; j < 4; j++) acc[i][j] = 0.f;

#pragma unroll 8
    for (int k = 0; k < K; k++) {
        float4 a  = *(const float4*)&Xs[k * 68 + 4 * ty];
        float4 b4 = *(const float4*)&Ws[k * CP + 4 * tx];
        acc[0][0] += a.x * b4.x; acc[0][1] += a.x * b4.y; acc[0][2] += a.x * b4.z; acc[0][3] += a.x * b4.w;
        acc[1][0] += a.y * b4.x; acc[1][1] += a.y * b4.y; acc[1][2] += a.y * b4.z; acc[1][3] += a.y * b4.w;
        acc[2][0] += a.z * b4.x; acc[2][1] += a.z * b4.y; acc[2][2] += a.z * b4.z; acc[2][3] += a.z * b4.w;
        acc[3][0] += a.w * b4.x; acc[3][1] += a.w * b4.y; acc[3][2] += a.w * b4.z; acc[3][3] += a.w * b4.w;
    }

    // write outputs
#pragma unroll
    for (int i = 0; i < 4; i++) {
        int node = base + 4 * ty + i;
        if (node >= NN) continue;
#pragma unroll
        for (int j = 0; j < 4; j++) {
            int c = 4 * tx + j;
            if (c < WC) {
                float v = acc[i][j];
                if (BIAS) v += bias[c];
                Out[(size_t)node * WC + c] = v;
            }
        }
    }

    // fused attention logits: asrc[n][hd] = sum_c out[n][c]*a_s[c], c in head hd
    if (ALPHA) {
        int hd = (4 * tx) >> 5;            // this thread's 4 cols lie in one head
        float w_s[4], w_d[4];
#pragma unroll
        for (int j = 0; j < 4; j++) { w_s[j] = a_s[4 * tx + j]; w_d[j] = a_d[4 * tx + j]; }
#pragma unroll
        for (int i = 0; i < 4; i++) {
            float pa = 0.f, pd = 0.f;
#pragma unroll
            for (int j = 0; j < 4; j++) { pa += acc[i][j] * w_s[j]; pd += acc[i][j] * w_d[j]; }
            atomicAdd(&sAs[4 * ty + i][hd], pa);
            atomicAdd(&sAd[4 * ty + i][hd], pd);
        }
        __syncthreads();
        if (tid < 64) {
            int node = base + tid;
            if (node < NN) {
                g_asrc[node] = make_float2(sAs[tid][0], sAs[tid][1]);
                g_adst[node] = make_float2(sAd[tid][0], sAd[tid][1]);
            }
        }
    }
}

// ---------------- launcher ---------------------------------------------------
extern "C" void kernel_launch(void* const* d_in, const int* in_sizes, int n_in,
                              void* d_out, int out_size)
{
    const float* node_feat = (const float*)d_in[0];
    const int*   edge      = (const int*)  d_in[1];
    const float* W1        = (const float*)d_in[2];
    const float* a_src1    = (const float*)d_in[3];
    const float* a_dst1    = (const float*)d_in[4];
    const float* b1        = (const float*)d_in[5];
    const float* bn_gamma  = (const float*)d_in[6];
    const float* bn_beta   = (const float*)d_in[7];
    const float* bn_mean   = (const float*)d_in[8];
    const float* bn_var    = (const float*)d_in[9];
    const float* W2        = (const float*)d_in[10];
    const float* a_src2    = (const float*)d_in[11];
    const float* a_dst2    = (const float*)d_in[12];
    const float* b2        = (const float*)d_in[13];
    const float* Wf        = (const float*)d_in[14];
    const float* bf        = (const float*)d_in[15];
    float* outp            = (float*)d_out;

    const int E = in_sizes[1] / 2;
    const int* src = edge;
    const int* dst = edge + E;

    const int GEMM_BLKS = (NN + 63) / 64;          // 1563
    const int WARP_BLKS = (NN + 7) / 8;            // 12500 (8 warps/block)
    const int E_BLKS    = (E + 255) / 256;
    const int N_BLKS    = (NN + 255) / 256;

    // dynamic smem sizes (single K chunk resident)
    const int SM1 = (FIN * 68 + FIN * 64) * 4;     // 67584 B  (needs attribute)
    const int SM2 = (HCC * 68 + HCC * 64) * 4;     // 33792 B
    const int SMF = (HCC * 68 + HCC * 48) * 4;     // 29696 B
    cudaFuncSetAttribute(k_gemm<FIN, 64, 64, false, true>,
                         cudaFuncAttributeMaxDynamicSharedMemorySize, SM1);

    // BN fold + CSR build
    k_bnprep<<<1, 64>>>(bn_gamma, bn_beta, bn_mean, bn_var);
    k_zero<<<N_BLKS, 256>>>();
    k_hist<<<E_BLKS, 256>>>(dst, E);
    k_scan1<<<SCAN_NB, 1024>>>();
    k_scan2<<<1, 128>>>();
    k_scan3<<<SCAN_NB, 1024>>>();
    k_scatter<<<E_BLKS, 256>>>(src, dst, E);

    // layer 1 (GEMM + fused alpha, then aggregate+BN+ELU)
    k_gemm<FIN, 64, 64, false, true><<<GEMM_BLKS, 256, SM1>>>(
        node_feat, W1, nullptr, g_h, a_src1, a_dst1);
    k_gat<<<WARP_BLKS, 256>>>(g_h, b1, g_x1, 0);

    // layer 2 (GEMM + fused alpha, then aggregate + JK max into g_x1)
    k_gemm<HCC, 64, 64, false, true><<<GEMM_BLKS, 256, SM2>>>(
        g_x1, W2, nullptr, g_h, a_src2, a_dst2);
    k_gat<<<WARP_BLKS, 256>>>(g_h, b2, g_x1, 1);

    // final projection 64 -> 40 (+bf)
    k_gemm<HCC, 48, OUTC, true, false><<<GEMM_BLKS, 192, SMF>>>(
        g_x1, Wf, bf, outp, nullptr, nullptr);
}